// round 1
// baseline (speedup 1.0000x reference)
#include <cuda_runtime.h>
#include <cstdint>
#include <cstddef>

// ---------------------------------------------------------------------------
// BottomUpIntegrator: N=2M cells -> K=16384 clusters -> organism summary
// Plan:
//   K1 cell_kernel     : per-cell MLP -> e=exp(w)  (fma.rn.f32x2 packed FP32)
//   K2 cluster_kernel  : warp-per-cluster segmented sums (seg_ids sorted ->
//                        binary search bounds), cluster stats + tiny MLP,
//                        writes cluster_out rows of d_out
//   K3 final_kernel    : single block, K-wide reduction -> self_model tail
// ---------------------------------------------------------------------------

#define NMAX 2097152
#define KMAX 16384

__device__ float g_e[NMAX];      // exp(w) per cell
__device__ float g_impc[KMAX];   // cluster importance
__device__ float g_cnt[KMAX];    // cluster counts

// ---- packed f32x2 helpers (sm_100a) ---------------------------------------
__device__ __forceinline__ unsigned long long pk2(float a, float b) {
    unsigned long long r;
    asm("mov.b64 %0,{%1,%2};" : "=l"(r) : "f"(a), "f"(b));
    return r;
}
__device__ __forceinline__ void upk2(unsigned long long v, float& a, float& b) {
    asm("mov.b64 {%0,%1},%2;" : "=f"(a), "=f"(b) : "l"(v));
}
__device__ __forceinline__ unsigned long long ffma2(unsigned long long a,
                                                    unsigned long long b,
                                                    unsigned long long c) {
    unsigned long long d;
    asm("fma.rn.f32x2 %0,%1,%2,%3;" : "=l"(d) : "l"(a), "l"(b), "l"(c));
    return d;
}

// ---------------------------------------------------------------------------
// Kernel 1: per-cell importance MLP.
//   feats = [state(32), arch(4)]  (36)
//   h = relu(feats @ W1 + b1)     (64)   -> packed f32x2, hidden in pairs
//   base = sigmoid(h @ W2 + b2)
//   w = clip(base*energy*phi, .01, 1) * energy * phi;  g_e = exp(w)
// ---------------------------------------------------------------------------
__global__ void __launch_bounds__(256) cell_kernel(
    const float* __restrict__ state, const float* __restrict__ arch,
    const float* __restrict__ energy, const float* __restrict__ phi,
    const float* __restrict__ W1, const float* __restrict__ b1,
    const float* __restrict__ W2, const float* __restrict__ b2, int N)
{
    __shared__ __align__(16) float W1s[36 * 64];
    __shared__ __align__(16) float b1s[64];
    __shared__ __align__(16) float W2s[64];
    __shared__ float b2s;

    int tid = threadIdx.x;
    for (int idx = tid; idx < 36 * 64; idx += 256) W1s[idx] = W1[idx];
    if (tid < 64) { b1s[tid] = b1[tid]; W2s[tid] = W2[tid]; }
    if (tid == 0) b2s = b2[0];
    __syncthreads();

    int i = blockIdx.x * 256 + tid;
    if (i >= N) return;

    // load the 36 features (thread-private row; L1 absorbs the 128B lines)
    float x[36];
    const float4* sp = (const float4*)(state + (size_t)i * 32);
#pragma unroll
    for (int q = 0; q < 8; q++) {
        float4 v = sp[q];
        x[q * 4 + 0] = v.x; x[q * 4 + 1] = v.y;
        x[q * 4 + 2] = v.z; x[q * 4 + 3] = v.w;
    }
    {
        float4 a4 = ((const float4*)arch)[i];
        x[32] = a4.x; x[33] = a4.y; x[34] = a4.z; x[35] = a4.w;
    }

    float dot = 0.f;
#pragma unroll 1
    for (int c = 0; c < 4; c++) {             // 4 chunks of 16 hidden units
        unsigned long long acc[8];
        const unsigned long long* b1p = (const unsigned long long*)(b1s + c * 16);
#pragma unroll
        for (int p = 0; p < 8; p++) acc[p] = b1p[p];
#pragma unroll
        for (int k = 0; k < 36; k++) {
            unsigned long long xk = pk2(x[k], x[k]);
            const unsigned long long* wr =
                (const unsigned long long*)(W1s + k * 64 + c * 16);
#pragma unroll
            for (int p = 0; p < 8; p++) acc[p] = ffma2(xk, wr[p], acc[p]);
        }
#pragma unroll
        for (int p = 0; p < 8; p++) {
            float lo, hi;
            upk2(acc[p], lo, hi);
            dot = fmaf(fmaxf(lo, 0.f), W2s[c * 16 + 2 * p], dot);
            dot = fmaf(fmaxf(hi, 0.f), W2s[c * 16 + 2 * p + 1], dot);
        }
    }

    float base = 1.f / (1.f + __expf(-(dot + b2s)));
    float ep = energy[i] * phi[i];
    float imp = fminf(fmaxf(base * ep, 0.01f), 1.f);
    // exp without max-subtraction is exact here: w in [0,1]
    g_e[i] = __expf(imp * ep);
}

// ---------------------------------------------------------------------------
// Kernel 2: warp-per-cluster segmented reductions + cluster MLP.
// seg_ids is sorted, so cluster k occupies a contiguous range found by
// binary search. Writes the 8-wide cluster_out row directly into d_out.
// ---------------------------------------------------------------------------
#define WARP_RED(v)                                           \
    do {                                                      \
        for (int _o = 16; _o; _o >>= 1)                       \
            (v) += __shfl_xor_sync(0xffffffffu, (v), _o);     \
    } while (0)

__global__ void __launch_bounds__(256) cluster_kernel(
    const int* __restrict__ seg, const float* __restrict__ arch,
    const float* __restrict__ surprise,
    const float* __restrict__ V1, const float* __restrict__ c1,
    const float* __restrict__ V2, const float* __restrict__ c2,
    float* __restrict__ out, int N, int K)
{
    int warp = (blockIdx.x * blockDim.x + threadIdx.x) >> 5;
    int lane = threadIdx.x & 31;
    if (warp >= K) return;
    int k = warp;

    // lower_bound(k) and lower_bound(k+1) on sorted seg ids
    int lo = 0, hi = N;
    while (lo < hi) { int mid = (lo + hi) >> 1; if (seg[mid] < k) lo = mid + 1; else hi = mid; }
    int begin = lo;
    hi = N;
    while (lo < hi) { int mid = (lo + hi) >> 1; if (seg[mid] < k + 1) lo = mid + 1; else hi = mid; }
    int end = lo;

    float se = 0.f, ss = 0.f;
    float sea0 = 0.f, sea1 = 0.f, sea2 = 0.f, sea3 = 0.f;
    float sa0 = 0.f, sa1 = 0.f, sa2 = 0.f, sa3 = 0.f;
    float sq0 = 0.f, sq1 = 0.f, sq2 = 0.f, sq3 = 0.f;

    for (int c = begin + lane; c < end; c += 32) {
        float e = g_e[c];
        float4 a = ((const float4*)arch)[c];
        float s = surprise[c];
        se += e;
        sea0 += e * a.x; sea1 += e * a.y; sea2 += e * a.z; sea3 += e * a.w;
        sa0 += a.x; sa1 += a.y; sa2 += a.z; sa3 += a.w;
        sq0 += a.x * a.x; sq1 += a.y * a.y; sq2 += a.z * a.z; sq3 += a.w * a.w;
        ss += s;
    }
    WARP_RED(se); WARP_RED(ss);
    WARP_RED(sea0); WARP_RED(sea1); WARP_RED(sea2); WARP_RED(sea3);
    WARP_RED(sa0); WARP_RED(sa1); WARP_RED(sa2); WARP_RED(sa3);
    WARP_RED(sq0); WARP_RED(sq1); WARP_RED(sq2); WARP_RED(sq3);

    float counts = (float)(end - begin);
    float cntc = fmaxf(counts, 1.f);
    float inv_se = (counts > 0.f) ? (1.f / se) : 0.f;
    float ag0 = sea0 * inv_se, ag1 = sea1 * inv_se;
    float ag2 = sea2 * inv_se, ag3 = sea3 * inv_se;

    // softmax over the 4 archetypes (stable)
    float m = fmaxf(fmaxf(ag0, ag1), fmaxf(ag2, ag3));
    float e0 = expf(ag0 - m), e1 = expf(ag1 - m);
    float e2 = expf(ag2 - m), e3 = expf(ag3 - m);
    float esum = e0 + e1 + e2 + e3;
    float r = 1.f / esum;
    float A0 = e0 * r, A1 = e1 * r, A2 = e2 * r, A3 = e3 * r;

    // unbiased per-cluster variance of arch
    float mn0 = sa0 / cntc, mn1 = sa1 / cntc, mn2 = sa2 / cntc, mn3 = sa3 / cntc;
    float dn = 1.f / fmaxf(counts - 1.f, 1.f);
    float v0 = (sq0 - counts * mn0 * mn0) * dn;
    float v1 = (sq1 - counts * mn1 * mn1) * dn;
    float v2 = (sq2 - counts * mn2 * mn2) * dn;
    float v3 = (sq3 - counts * mn3 * mn3) * dn;
    float var_m = (v0 + v1 + v2 + v3) * 0.25f;

    float phi_c = 1.f - fminf(1.f, var_m * 2.f);
    float coh   = 1.f - var_m;
    float pred  = ss / cntc;
    float integ = phi_c * (1.f - pred);

    // cluster MLP: cfeat(7) @ V1(7x32) -> relu -> @ V2(32x1) -> sigmoid
    float cf0 = A0, cf1 = A1, cf2 = A2, cf3 = A3;
    float cf4 = phi_c, cf5 = coh, cf6 = fminf(1.f, counts * (1.f / 20.f));
    float hc = c1[lane];
    hc = fmaf(cf0, V1[0 * 32 + lane], hc);
    hc = fmaf(cf1, V1[1 * 32 + lane], hc);
    hc = fmaf(cf2, V1[2 * 32 + lane], hc);
    hc = fmaf(cf3, V1[3 * 32 + lane], hc);
    hc = fmaf(cf4, V1[4 * 32 + lane], hc);
    hc = fmaf(cf5, V1[5 * 32 + lane], hc);
    hc = fmaf(cf6, V1[6 * 32 + lane], hc);
    hc = fmaxf(hc, 0.f);
    float pre = hc * V2[lane];
    WARP_RED(pre);
    float basec = 1.f / (1.f + expf(-(pre + c2[0])));
    float impc = fminf(fmaxf(basec * phi_c, 0.01f), 1.f);

    if (lane == 0) {
        float* row = out + (size_t)k * 8;
        row[0] = A0; row[1] = A1; row[2] = A2; row[3] = A3;
        row[4] = phi_c; row[5] = coh; row[6] = pred; row[7] = integ;
        g_impc[k] = impc;
        g_cnt[k] = counts;
    }
}

// ---------------------------------------------------------------------------
// Kernel 3: organism-level summary (single block).
// wc = softmax over valid impc (impc <= 1 so exp without max is exact).
// ---------------------------------------------------------------------------
__device__ float block_sum(float v, float* sh) {
    int t = threadIdx.x;
    sh[t] = v;
    __syncthreads();
    for (int o = 128; o; o >>= 1) {
        if (t < o) sh[t] += sh[t + o];
        __syncthreads();
    }
    float r = sh[0];
    __syncthreads();
    return r;
}

__global__ void __launch_bounds__(256) final_kernel(
    const float* __restrict__ cl, float* __restrict__ tail, int K)
{
    __shared__ float sh[256];
    __shared__ int smask;
    if (threadIdx.x == 0) smask = 0;
    __syncthreads();

    float denom = 0.f, s0 = 0.f, s1 = 0.f, s2 = 0.f, s3 = 0.f;
    float sphi = 0.f, scoh = 0.f, nv = 0.f;
    int mask = 0;

    for (int k = threadIdx.x; k < K; k += 256) {
        float cnt = g_cnt[k];
        if (cnt > 0.f) {
            const float* row = cl + (size_t)k * 8;
            float w = expf(g_impc[k]);
            float a0 = row[0], a1 = row[1], a2 = row[2], a3 = row[3];
            denom += w;
            s0 += w * a0; s1 += w * a1; s2 += w * a2; s3 += w * a3;
            sphi += row[4]; scoh += row[5]; nv += 1.f;
            int sp = 0; float best = a0;                 // first-max argmax
            if (a1 > best) { best = a1; sp = 1; }
            if (a2 > best) { best = a2; sp = 2; }
            if (a3 > best) { best = a3; sp = 3; }
            mask |= (1 << sp);
        }
    }
    atomicOr(&smask, mask);
    denom = block_sum(denom, sh);
    s0 = block_sum(s0, sh); s1 = block_sum(s1, sh);
    s2 = block_sum(s2, sh); s3 = block_sum(s3, sh);
    sphi = block_sum(sphi, sh); scoh = block_sum(scoh, sh);
    nv = block_sum(nv, sh);

    if (threadIdx.x == 0) {
        float rd = 1.f / denom;
        float g0 = s0 * rd, g1 = s1 * rd, g2 = s2 * rd, g3 = s3 * rd;
        float m = fmaxf(fmaxf(g0, g1), fmaxf(g2, g3));
        float e0 = expf(g0 - m), e1 = expf(g1 - m);
        float e2 = expf(g2 - m), e3 = expf(g3 - m);
        float es = e0 + e1 + e2 + e3;
        float nvalid = fmaxf(nv, 1.f);
        float avg_phi = sphi / nvalid;
        int unique = __popc(smask);
        float phi_global = fminf(1.f, avg_phi * (0.5f + 0.5f * (float)unique * 0.25f));
        float vert = scoh / nvalid;
        tail[0] = e0 / es; tail[1] = e1 / es; tail[2] = e2 / es; tail[3] = e3 / es;
        tail[4] = phi_global;
        tail[5] = vert;
    }
}

// ---------------------------------------------------------------------------
extern "C" void kernel_launch(void* const* d_in, const int* in_sizes, int n_in,
                              void* d_out, int out_size)
{
    const float* state    = (const float*)d_in[0];
    const float* arch     = (const float*)d_in[1];
    const float* energy   = (const float*)d_in[2];
    const float* phi      = (const float*)d_in[3];
    const float* surprise = (const float*)d_in[4];
    const int*   seg      = (const int*)d_in[5];

    // locate W1 (size 36*64 = 2304) to be robust to the scalar n_clusters input
    int woff = 6;
    for (int j = 6; j < n_in; j++) {
        if (in_sizes[j] == 2304) { woff = j; break; }
    }
    const float* W1 = (const float*)d_in[woff + 0];
    const float* b1 = (const float*)d_in[woff + 1];
    const float* W2 = (const float*)d_in[woff + 2];
    const float* b2 = (const float*)d_in[woff + 3];
    const float* V1 = (const float*)d_in[woff + 4];
    const float* c1 = (const float*)d_in[woff + 5];
    const float* V2 = (const float*)d_in[woff + 6];
    const float* c2 = (const float*)d_in[woff + 7];

    int N = in_sizes[2];                 // energy element count
    int K = (out_size - 6) / 8;          // cluster_out rows
    float* out = (float*)d_out;

    cell_kernel<<<(N + 255) / 256, 256>>>(state, arch, energy, phi,
                                          W1, b1, W2, b2, N);
    int warps = K;
    cluster_kernel<<<(warps * 32 + 255) / 256, 256>>>(seg, arch, surprise,
                                                      V1, c1, V2, c2,
                                                      out, N, K);
    final_kernel<<<1, 256>>>(out, out + (size_t)K * 8, K);
}

// round 5
// speedup vs baseline: 2.2603x; 2.2603x over previous
#include <cuda_runtime.h>
#include <cuda_bf16.h>
#include <cstdint>
#include <cstddef>

// ---------------------------------------------------------------------------
// BottomUpIntegrator — R5 (retry of the HMMA design after two infra failures)
//   K0 bounds_kernel  : sorted seg_ids -> g_off[k] cluster start offsets
//   K1 cell_mma_kernel: m16n8k16 bf16 HMMA, W1 in registers, h never hits
//                       memory: layer-2 dot on C fragments + quad shuffle
//   K2 cluster_kernel : warp-per-cluster segmented sums + cluster MLP
//   K3 final_kernel   : reduce per-block partials -> self_model tail
// ---------------------------------------------------------------------------

#define NMAX 2097152
#define KMAX 16384
#define PBMAX (KMAX / 8 + 1)

__device__ float g_e[NMAX];              // exp(w) per cell
__device__ int   g_off[KMAX + 1];        // cluster start offsets
__device__ float g_part[PBMAX * 9];      // per-block partial sums
__device__ int   g_maskp[PBMAX];         // per-block presence masks

// ===========================================================================
// K0: segment start offsets from sorted seg_ids
// ===========================================================================
__global__ void __launch_bounds__(256) bounds_kernel(const int* __restrict__ seg,
                                                     int N, int K) {
    int i = blockIdx.x * 256 + threadIdx.x;
    if (i >= N) return;
    int cur = seg[i];
    int prev = (i == 0) ? -1 : seg[i - 1];
    for (int k = prev + 1; k <= cur; k++) g_off[k] = i;
    if (i == N - 1)
        for (int k = cur + 1; k <= K; k++) g_off[k] = N;
}

// ===========================================================================
// K1: cell MLP with mma.sync.m16n8k16.row.col.f32.bf16.bf16.f32
//   h[16 cells x 64 hidden] = feats[16 x 48] @ W1pad[48 x 64]
//   feats: cols 0-31 = state, 32-35 = arch, 36-47 = 0
//   Fragment layouts (PTX ISA): g = lane>>2, t = lane&3
//     A: a0 row g   cols 2t,2t+1 | a1 row g+8 cols 2t,2t+1
//        a2 row g   cols 2t+8,+9 | a3 row g+8 cols 2t+8,+9
//     B: b0 k 2t,2t+1 n g | b1 k 2t+8,2t+9 n g
//     C: c0,c1 row g cols 2t,2t+1 | c2,c3 row g+8 cols 2t,2t+1
// ===========================================================================
#define WARPS_PER_CTA 8
#define TILE_ITERS 8                      // 16-cell tiles per warp
#define CELLS_PER_CTA (WARPS_PER_CTA * 16 * TILE_ITERS)   // 1024

__device__ __forceinline__ uint32_t pack_bf2(float a, float b) {
    __nv_bfloat162 h = __floats2bfloat162_rn(a, b);
    return *(uint32_t*)&h;
}

// packed bf16x2 of features (col0, col0+1) for one cell; col0 even
__device__ __forceinline__ uint32_t load_feat2(const float* __restrict__ state,
                                               const float* __restrict__ arch,
                                               int cell, int col0, int N) {
    float f0 = 0.f, f1 = 0.f;
    if (cell < N) {
        if (col0 < 32) {
            float2 v = *(const float2*)(state + (size_t)cell * 32 + col0);
            f0 = v.x; f1 = v.y;
        } else if (col0 < 36) {
            float2 v = *(const float2*)(arch + (size_t)cell * 4 + (col0 - 32));
            f0 = v.x; f1 = v.y;
        }
    }
    return pack_bf2(f0, f1);
}

__device__ __forceinline__ void mma16816(float& c0, float& c1, float& c2, float& c3,
                                         uint32_t a0, uint32_t a1, uint32_t a2,
                                         uint32_t a3, uint32_t b0, uint32_t b1) {
    asm volatile(
        "mma.sync.aligned.m16n8k16.row.col.f32.bf16.bf16.f32 "
        "{%0,%1,%2,%3}, {%4,%5,%6,%7}, {%8,%9}, {%0,%1,%2,%3};"
        : "+f"(c0), "+f"(c1), "+f"(c2), "+f"(c3)
        : "r"(a0), "r"(a1), "r"(a2), "r"(a3), "r"(b0), "r"(b1));
}

__global__ void __launch_bounds__(256) cell_mma_kernel(
    const float* __restrict__ state, const float* __restrict__ arch,
    const float* __restrict__ energy, const float* __restrict__ phi,
    const float* __restrict__ W1, const float* __restrict__ b1,
    const float* __restrict__ W2, const float* __restrict__ b2, int N)
{
    __shared__ float sb1[64], sW2[64], sb2;

    const int tid = threadIdx.x;
    const int warp = tid >> 5, lane = tid & 31;
    const int g = lane >> 2, t = lane & 3;

    if (tid < 64) { sb1[tid] = b1[tid]; sW2[tid] = W2[tid]; }
    if (tid == 64) sb2 = b2[0];
    __syncthreads();

    // ---- preload W1 fragments: Bf[s][j] for k-step s, n-tile j ----
    uint32_t Bf[3][8][2];
#pragma unroll
    for (int s = 0; s < 3; s++) {
        const int k0 = s * 16 + t * 2;
#pragma unroll
        for (int j = 0; j < 8; j++) {
            const int n = j * 8 + g;
            float w00 = (k0     < 36) ? W1[(k0)     * 64 + n] : 0.f;
            float w01 = (k0 + 1 < 36) ? W1[(k0 + 1) * 64 + n] : 0.f;
            float w10 = (k0 + 8 < 36) ? W1[(k0 + 8) * 64 + n] : 0.f;
            float w11 = (k0 + 9 < 36) ? W1[(k0 + 9) * 64 + n] : 0.f;
            Bf[s][j][0] = pack_bf2(w00, w01);
            Bf[s][j][1] = pack_bf2(w10, w11);
        }
    }

    const int warp_base = blockIdx.x * CELLS_PER_CTA + warp * (16 * TILE_ITERS);

    for (int it = 0; it < TILE_ITERS; it++) {
        const int base = warp_base + it * 16;     // warp-uniform
        if (base >= N) break;
        const int cg = base + g;        // row g cell
        const int cg8 = cg + 8;         // row g+8 cell

        // accumulators, bias folded in (cols 2t+... per n-tile)
        float acc[8][4];
#pragma unroll
        for (int j = 0; j < 8; j++) {
            float bb0 = sb1[j * 8 + t * 2];
            float bb1 = sb1[j * 8 + t * 2 + 1];
            acc[j][0] = bb0; acc[j][1] = bb1;
            acc[j][2] = bb0; acc[j][3] = bb1;
        }

#pragma unroll
        for (int s = 0; s < 3; s++) {
            const int k0 = s * 16 + t * 2;
            uint32_t a0 = load_feat2(state, arch, cg,  k0,     N);
            uint32_t a1 = load_feat2(state, arch, cg8, k0,     N);
            uint32_t a2 = load_feat2(state, arch, cg,  k0 + 8, N);
            uint32_t a3 = load_feat2(state, arch, cg8, k0 + 8, N);
#pragma unroll
            for (int j = 0; j < 8; j++)
                mma16816(acc[j][0], acc[j][1], acc[j][2], acc[j][3],
                         a0, a1, a2, a3, Bf[s][j][0], Bf[s][j][1]);
        }

        // ---- layer 2: relu(h) . W2, reduce across the quad ----
        float d0 = 0.f, d1 = 0.f;
#pragma unroll
        for (int j = 0; j < 8; j++) {
            float w2a = sW2[j * 8 + t * 2];
            float w2b = sW2[j * 8 + t * 2 + 1];
            d0 = fmaf(fmaxf(acc[j][0], 0.f), w2a, d0);
            d0 = fmaf(fmaxf(acc[j][1], 0.f), w2b, d0);
            d1 = fmaf(fmaxf(acc[j][2], 0.f), w2a, d1);
            d1 = fmaf(fmaxf(acc[j][3], 0.f), w2b, d1);
        }
        d0 += __shfl_xor_sync(0xffffffffu, d0, 1);
        d1 += __shfl_xor_sync(0xffffffffu, d1, 1);
        d0 += __shfl_xor_sync(0xffffffffu, d0, 2);
        d1 += __shfl_xor_sync(0xffffffffu, d1, 2);

        if (t == 0) {
            if (cg < N) {
                float bs = 1.f / (1.f + __expf(-(d0 + sb2)));
                float ep = energy[cg] * phi[cg];
                float imp = fminf(fmaxf(bs * ep, 0.01f), 1.f);
                g_e[cg] = __expf(imp * ep);        // w in [0,1]: exp w/o max exact
            }
            if (cg8 < N) {
                float bs = 1.f / (1.f + __expf(-(d1 + sb2)));
                float ep = energy[cg8] * phi[cg8];
                float imp = fminf(fmaxf(bs * ep, 0.01f), 1.f);
                g_e[cg8] = __expf(imp * ep);
            }
        }
    }
}

// ===========================================================================
// K2: warp-per-cluster segmented sums + cluster MLP + per-block partials
// ===========================================================================
#define WARP_RED(v)                                           \
    do {                                                      \
        for (int _o = 16; _o; _o >>= 1)                       \
            (v) += __shfl_xor_sync(0xffffffffu, (v), _o);     \
    } while (0)

__global__ void __launch_bounds__(256) cluster_kernel(
    const float* __restrict__ arch, const float* __restrict__ surprise,
    const float* __restrict__ V1, const float* __restrict__ c1,
    const float* __restrict__ V2, const float* __restrict__ c2,
    float* __restrict__ out, int K)
{
    __shared__ float sp[8][8];   // per-warp: den, s0..s3, sphi, scoh, nv
    __shared__ int smk[8];

    const int wip = threadIdx.x >> 5;
    const int lane = threadIdx.x & 31;
    const int k = blockIdx.x * 8 + wip;

    if (lane == 0) {
#pragma unroll
        for (int j = 0; j < 8; j++) sp[wip][j] = 0.0f;
        smk[wip] = 0;
    }
    __syncwarp();

    if (k < K) {
        const int begin = g_off[k], end = g_off[k + 1];

        float se = 0.f, ss = 0.f;
        float sea0 = 0.f, sea1 = 0.f, sea2 = 0.f, sea3 = 0.f;
        float sa0 = 0.f, sa1 = 0.f, sa2 = 0.f, sa3 = 0.f;
        float sq0 = 0.f, sq1 = 0.f, sq2 = 0.f, sq3 = 0.f;

        for (int c = begin + lane; c < end; c += 32) {
            float e = g_e[c];
            float4 a = ((const float4*)arch)[c];
            se += e; ss += surprise[c];
            sea0 += e * a.x; sea1 += e * a.y; sea2 += e * a.z; sea3 += e * a.w;
            sa0 += a.x; sa1 += a.y; sa2 += a.z; sa3 += a.w;
            sq0 += a.x * a.x; sq1 += a.y * a.y; sq2 += a.z * a.z; sq3 += a.w * a.w;
        }
        WARP_RED(se); WARP_RED(ss);
        WARP_RED(sea0); WARP_RED(sea1); WARP_RED(sea2); WARP_RED(sea3);
        WARP_RED(sa0); WARP_RED(sa1); WARP_RED(sa2); WARP_RED(sa3);
        WARP_RED(sq0); WARP_RED(sq1); WARP_RED(sq2); WARP_RED(sq3);

        float counts = (float)(end - begin);
        float cntc = fmaxf(counts, 1.f);
        float inv_se = (counts > 0.f) ? (1.f / se) : 0.f;
        float ag0 = sea0 * inv_se, ag1 = sea1 * inv_se;
        float ag2 = sea2 * inv_se, ag3 = sea3 * inv_se;

        float m = fmaxf(fmaxf(ag0, ag1), fmaxf(ag2, ag3));
        float e0 = expf(ag0 - m), e1 = expf(ag1 - m);
        float e2 = expf(ag2 - m), e3 = expf(ag3 - m);
        float r = 1.f / (e0 + e1 + e2 + e3);
        float A0 = e0 * r, A1 = e1 * r, A2 = e2 * r, A3 = e3 * r;

        float mn0 = sa0 / cntc, mn1 = sa1 / cntc, mn2 = sa2 / cntc, mn3 = sa3 / cntc;
        float dn = 1.f / fmaxf(counts - 1.f, 1.f);
        float v0 = (sq0 - counts * mn0 * mn0) * dn;
        float v1 = (sq1 - counts * mn1 * mn1) * dn;
        float v2 = (sq2 - counts * mn2 * mn2) * dn;
        float v3 = (sq3 - counts * mn3 * mn3) * dn;
        float var_m = (v0 + v1 + v2 + v3) * 0.25f;

        float phi_c = 1.f - fminf(1.f, var_m * 2.f);
        float coh   = 1.f - var_m;
        float pred  = ss / cntc;
        float integ = phi_c * (1.f - pred);

        // cluster MLP: cfeat(7) @ V1(7x32) -> relu -> @ V2 -> sigmoid
        float cf6 = fminf(1.f, counts * (1.f / 20.f));
        float hc = c1[lane];
        hc = fmaf(A0, V1[0 * 32 + lane], hc);
        hc = fmaf(A1, V1[1 * 32 + lane], hc);
        hc = fmaf(A2, V1[2 * 32 + lane], hc);
        hc = fmaf(A3, V1[3 * 32 + lane], hc);
        hc = fmaf(phi_c, V1[4 * 32 + lane], hc);
        hc = fmaf(coh, V1[5 * 32 + lane], hc);
        hc = fmaf(cf6, V1[6 * 32 + lane], hc);
        float pre = fmaxf(hc, 0.f) * V2[lane];
        WARP_RED(pre);
        float basec = 1.f / (1.f + expf(-(pre + c2[0])));
        float impc = fminf(fmaxf(basec * phi_c, 0.01f), 1.f);

        if (lane == 0) {
            float* rowp = out + (size_t)k * 8;
            rowp[0] = A0; rowp[1] = A1; rowp[2] = A2; rowp[3] = A3;
            rowp[4] = phi_c; rowp[5] = coh; rowp[6] = pred; rowp[7] = integ;
            if (counts > 0.f) {
                float w = expf(impc);              // impc <= 1: exact vs max-sub
                sp[wip][0] = w;
                sp[wip][1] = w * A0; sp[wip][2] = w * A1;
                sp[wip][3] = w * A2; sp[wip][4] = w * A3;
                sp[wip][5] = phi_c; sp[wip][6] = coh; sp[wip][7] = 1.f;
                int spx = 0; float best = A0;
                if (A1 > best) { best = A1; spx = 1; }
                if (A2 > best) { best = A2; spx = 2; }
                if (A3 > best) { best = A3; spx = 3; }
                smk[wip] = 1 << spx;
            }
        }
    }
    __syncthreads();

    if (threadIdx.x < 9) {
        int j = threadIdx.x;
        if (j < 8) {
            float s = 0.f;
#pragma unroll
            for (int wv = 0; wv < 8; wv++) s += sp[wv][j];
            g_part[(size_t)blockIdx.x * 9 + j] = s;
        } else {
            int mk = 0;
#pragma unroll
            for (int wv = 0; wv < 8; wv++) mk |= smk[wv];
            g_maskp[blockIdx.x] = mk;
        }
    }
}

// ===========================================================================
// K3: reduce per-block partials -> self_model tail
// ===========================================================================
__global__ void __launch_bounds__(256) final_kernel(float* __restrict__ tail,
                                                    int nblocks) {
    __shared__ float sh[256];
    __shared__ int smask;
    if (threadIdx.x == 0) smask = 0;
    __syncthreads();

    float acc[8] = {0.f, 0.f, 0.f, 0.f, 0.f, 0.f, 0.f, 0.f};
    int mask = 0;
    for (int b = threadIdx.x; b < nblocks; b += 256) {
#pragma unroll
        for (int j = 0; j < 8; j++) acc[j] += g_part[(size_t)b * 9 + j];
        mask |= g_maskp[b];
    }
    atomicOr(&smask, mask);

#pragma unroll
    for (int j = 0; j < 8; j++) {
        int tt = threadIdx.x;
        sh[tt] = acc[j];
        __syncthreads();
        for (int o = 128; o; o >>= 1) {
            if (tt < o) sh[tt] += sh[tt + o];
            __syncthreads();
        }
        acc[j] = sh[0];
        __syncthreads();
    }

    if (threadIdx.x == 0) {
        float rd = 1.f / acc[0];
        float g0 = acc[1] * rd, g1 = acc[2] * rd, g2 = acc[3] * rd, g3 = acc[4] * rd;
        float m = fmaxf(fmaxf(g0, g1), fmaxf(g2, g3));
        float e0 = expf(g0 - m), e1 = expf(g1 - m);
        float e2 = expf(g2 - m), e3 = expf(g3 - m);
        float es = e0 + e1 + e2 + e3;
        float nvalid = fmaxf(acc[7], 1.f);
        float avg_phi = acc[5] / nvalid;
        int unique = __popc(smask);
        float phi_global = fminf(1.f, avg_phi * (0.5f + 0.5f * (float)unique * 0.25f));
        float vert = acc[6] / nvalid;
        tail[0] = e0 / es; tail[1] = e1 / es; tail[2] = e2 / es; tail[3] = e3 / es;
        tail[4] = phi_global;
        tail[5] = vert;
    }
}

// ===========================================================================
extern "C" void kernel_launch(void* const* d_in, const int* in_sizes, int n_in,
                              void* d_out, int out_size)
{
    const float* state    = (const float*)d_in[0];
    const float* arch     = (const float*)d_in[1];
    const float* energy   = (const float*)d_in[2];
    const float* phi      = (const float*)d_in[3];
    const float* surprise = (const float*)d_in[4];
    const int*   seg      = (const int*)d_in[5];

    int woff = 6;
    for (int j = 6; j < n_in; j++)
        if (in_sizes[j] == 2304) { woff = j; break; }
    const float* W1 = (const float*)d_in[woff + 0];
    const float* b1 = (const float*)d_in[woff + 1];
    const float* W2 = (const float*)d_in[woff + 2];
    const float* b2 = (const float*)d_in[woff + 3];
    const float* V1 = (const float*)d_in[woff + 4];
    const float* c1 = (const float*)d_in[woff + 5];
    const float* V2 = (const float*)d_in[woff + 6];
    const float* c2 = (const float*)d_in[woff + 7];

    int N = in_sizes[2];
    int K = (out_size - 6) / 8;
    float* out = (float*)d_out;

    bounds_kernel<<<(N + 255) / 256, 256>>>(seg, N, K);
    cell_mma_kernel<<<(N + CELLS_PER_CTA - 1) / CELLS_PER_CTA, 256>>>(
        state, arch, energy, phi, W1, b1, W2, b2, N);
    int cblocks = (K + 7) / 8;
    cluster_kernel<<<cblocks, 256>>>(arch, surprise, V1, c1, V2, c2, out, K);
    final_kernel<<<1, 256>>>(out + (size_t)K * 8, cblocks);
}